// round 16
// baseline (speedup 1.0000x reference)
#include <cuda_runtime.h>
#include <cuda_fp16.h>
#include <mma.h>
#include <math.h>

using namespace nvcuda;

#define Bq     64
#define Nq     384
#define NFEAT  16
#define Eq     3
#define NHID   128
#define ST_HID 64
#define ST_OUT 16
#define MFLAT  (Bq * Nq)
#define SCALE_DN 0.0625f
#define SCALE_UP 16.0f

// ---------------- device scratch ----------------
__device__ __half g_adjhi[Bq * Eq * Nq * Nq];
__device__ __half g_adjlo[Bq * Eq * Nq * Nq];
__device__ __half g_supphi[Bq * Eq * Nq * NHID];
__device__ __half g_supplo[Bq * Eq * Nq * NHID];
__device__ __half g_s64hi[Bq * Eq * Nq * ST_HID];
__device__ __half g_s64lo[Bq * Eq * Nq * ST_HID];
__device__ float  g_oe[Bq * Eq * Nq * NHID];
__device__ __half g_hhi[MFLAT * NHID];
__device__ __half g_hlo[MFLAT * NHID];
__device__ __half g_h0hi[MFLAT * NFEAT];
__device__ __half g_h0lo[MFLAT * NFEAT];
__device__ __half g_t1hi[Bq * Eq * Nq * NFEAT];
__device__ __half g_t1lo[Bq * Eq * Nq * NFEAT];
__device__ __half g_w1hi[Eq * NFEAT * NHID];
__device__ __half g_w1lo[Eq * NFEAT * NHID];
__device__ __half g_w2hi[Eq * NHID * NHID];
__device__ __half g_w2lo[Eq * NHID * NHID];
__device__ __half g_w31hi[Eq * NHID * ST_HID];
__device__ __half g_w31lo[Eq * NHID * ST_HID];

// ---------------- fp16 Dekker split ----------------
__device__ __forceinline__ void split1h(float v, __half& h, __half& l) {
    h = __float2half_rn(v);
    l = __float2half_rn(v - __half2float(h));
}
struct alignas(16) H8 { __half v[8]; };

// ---------------- prep kernels (3 launches, for ncu slot alignment) ----------------
#define W2BLK ((Eq * NHID * NHID) / 8 / 256)   // 24
#define W1BLK ((Eq * NFEAT * NHID) / 8 / 256)  // 3
__global__ void prep_w_kernel(const float* __restrict__ gc2_w,
                              const float* __restrict__ gc1_w,
                              __half* __restrict__ w2hi, __half* __restrict__ w2lo,
                              __half* __restrict__ w1hi, __half* __restrict__ w1lo) {
    int bx = blockIdx.x;
    const float* src;
    __half *hi, *lo;
    int i;
    if (bx < W2BLK) { src = gc2_w; hi = w2hi; lo = w2lo; i = bx * 256 + threadIdx.x; }
    else { src = gc1_w; hi = w1hi; lo = w1lo; i = (bx - W2BLK) * 256 + threadIdx.x; }
    float4 a = *(const float4*)(src + (size_t)i * 8);
    float4 b = *(const float4*)(src + (size_t)i * 8 + 4);
    float vv[8] = {a.x, a.y, a.z, a.w, b.x, b.y, b.z, b.w};
    H8 H, L;
#pragma unroll
    for (int j = 0; j < 8; j++) split1h(vv[j], H.v[j], L.v[j]);
    *(H8*)(hi + (size_t)i * 8) = H;
    *(H8*)(lo + (size_t)i * 8) = L;
}

__global__ void prep_w31_kernel(const float* __restrict__ gc3_w,
                                const float* __restrict__ st_w1,
                                __half* __restrict__ w31hi, __half* __restrict__ w31lo) {
    int idx = blockIdx.x * 256 + threadIdx.x;
    int k = idx & 63, d = (idx >> 6) & 127, e = idx >> 13;
    float acc = 0.f;
#pragma unroll 8
    for (int h = 0; h < NHID; h++)
        acc += gc3_w[((size_t)(e * NHID + d)) * NHID + h] * st_w1[k * NHID + h];
    split1h(acc, w31hi[(size_t)(e * NHID + d) * ST_HID + k],
                 w31lo[(size_t)(e * NHID + d) * ST_HID + k]);
}

__global__ void prep_h0_kernel(const float* __restrict__ emb_w,
                               const float* __restrict__ x,
                               __half* __restrict__ h0hi, __half* __restrict__ h0lo) {
    int idx = blockIdx.x * 256 + threadIdx.x;
    int row = idx >> 4, f = idx & 15;
    float acc = 0.f;
#pragma unroll
    for (int d = 0; d < NFEAT; d++)
        acc += x[(size_t)row * NFEAT + d] * emb_w[f * NFEAT + d];
    split1h(acc * SCALE_DN, h0hi[idx], h0lo[idx]);
}

// hsum_split
__global__ void hsum_split_kernel(const float* __restrict__ oe,
                                  __half* __restrict__ hhi, __half* __restrict__ hlo) {
    int idx = blockIdx.x * 256 + threadIdx.x;
    size_t e8 = (size_t)idx * 8;
    int row = (int)(e8 >> 7), c = (int)(e8 & 127);
    int b = row / Nq, n = row % Nq;
    const size_t eS = (size_t)Nq * NHID;
    const float* base = oe + ((size_t)(b * Eq) * Nq + n) * NHID + c;
    H8 H, L;
#pragma unroll
    for (int q = 0; q < 2; q++) {
        float4 v0 = *(const float4*)(base + q * 4);
        float4 v1 = *(const float4*)(base + eS + q * 4);
        float4 v2 = *(const float4*)(base + 2 * eS + q * 4);
        float s[4] = {(v0.x + v1.x + v2.x) * SCALE_DN, (v0.y + v1.y + v2.y) * SCALE_DN,
                      (v0.z + v1.z + v2.z) * SCALE_DN, (v0.w + v1.w + v2.w) * SCALE_DN};
#pragma unroll
        for (int j = 0; j < 4; j++) split1h(s[j], H.v[q * 4 + j], L.v[q * 4 + j]);
    }
    *(H8*)(hhi + e8) = H;
    *(H8*)(hlo + e8) = L;
}

// ---------------- cp.async ----------------
__device__ __forceinline__ void cpa16(unsigned s, const void* g) {
    asm volatile("cp.async.cg.shared.global [%0], [%1], 16;" :: "r"(s), "l"(g));
}
#define CPA_COMMIT() asm volatile("cp.async.commit_group;" ::: "memory")
#define CPA_WAIT(N)  asm volatile("cp.async.wait_group %0;" :: "n"(N) : "memory")

typedef wmma::fragment<wmma::matrix_a, 16, 16, 16, __half, wmma::row_major> AF;
typedef wmma::fragment<wmma::matrix_b, 16, 16, 16, __half, wmma::row_major> BF;
typedef wmma::fragment<wmma::accumulator, 16, 16, 16, float> CF;

// ---------------- smem layouts (halfs) ----------------
#define AG_LDA 40
#define LDB_H  136
#define H_AHI 0
#define H_ALO (128 * AG_LDA)
#define H_BHI (2 * 128 * AG_LDA)
#define H_BLO (H_BHI + 32 * LDB_H)
#define STAGE_H (H_BLO + 32 * LDB_H)       // 18944
#define AG_SMEM (2 * STAGE_H * 2)          // 75776 B
#define LDB64 72
#define B64_BHI (2 * 128 * AG_LDA)
#define B64_BLO (B64_BHI + 32 * LDB64)
#define STAGE64_H (B64_BLO + 32 * LDB64)
#define A64_SMEM (2 * STAGE64_H * 2)       // 59392 B
// agg16_split v3: 2 A stages (128x32 ld40 hi/lo each) + resident h0 (384x16 hi/lo)
#define A16_STAGE (2 * 128 * AG_LDA)       // 10240 halfs per A stage (hi+lo)
#define A16_BHI (2 * A16_STAGE)            // 20480
#define A16_BLO (A16_BHI + Nq * NFEAT)     // 26624
#define A16_SMEM ((A16_BLO + Nq * NFEAT) * 2)  // 65536 B
// support1
#define S1_LDA 24
#define S1_AHI 0
#define S1_ALO (128 * S1_LDA)
#define S1_BHI (2 * 128 * S1_LDA)
#define S1_BLO (S1_BHI + 16 * LDB_H)
#define S1_SMEM ((S1_BLO + 16 * LDB_H) * 2)

// ---------------------------------------------------------------------------
// Generic loaders / mainloops
// ---------------------------------------------------------------------------
__device__ __forceinline__ void gm_load_stage(unsigned sb, const __half* aH,
                                              const __half* aL, const __half* bH,
                                              const __half* bL, int kt, int tid,
                                              int aStride) {
#pragma unroll
    for (int t = 0; t < 2; t++) {
        int idx = tid + t * 256;
        int r = idx >> 2, c8 = idx & 3;
        size_t g = (size_t)r * aStride + kt * 32 + c8 * 8;
        cpa16(sb + (H_AHI + r * AG_LDA + c8 * 8) * 2, aH + g);
        cpa16(sb + (H_ALO + r * AG_LDA + c8 * 8) * 2, aL + g);
    }
#pragma unroll
    for (int t = 0; t < 2; t++) {
        int idx = tid + t * 256;
        int r = idx >> 4, c8 = idx & 15;
        size_t g = (size_t)(kt * 32 + r) * NHID + c8 * 8;
        cpa16(sb + (H_BHI + r * LDB_H + c8 * 8) * 2, bH + g);
        cpa16(sb + (H_BLO + r * LDB_H + c8 * 8) * 2, bL + g);
    }
}

template <int KT>
__device__ __forceinline__ void gemm_mainloop(
        __half* smh, unsigned sbase, const __half* aH, const __half* aL,
        const __half* bH, const __half* bL, int aStride, int tid,
        int wm, int wn, CF (&c)[2][4]) {
    gm_load_stage(sbase, aH, aL, bH, bL, 0, tid, aStride);
    CPA_COMMIT();
    for (int kt = 0; kt < KT; kt++) {
        if (kt + 1 < KT) {
            gm_load_stage(sbase + ((kt + 1) & 1) * STAGE_H * 2,
                          aH, aL, bH, bL, kt + 1, tid, aStride);
            CPA_COMMIT();
            CPA_WAIT(1);
        } else {
            CPA_WAIT(0);
        }
        __syncthreads();

        const __half* S = smh + (kt & 1) * STAGE_H;
#pragma unroll
        for (int k16 = 0; k16 < 2; k16++) {
            AF afH[2], afL[2];
#pragma unroll
            for (int i = 0; i < 2; i++) {
                const __half* p = S + H_AHI + (wm * 32 + i * 16) * AG_LDA + k16 * 16;
                wmma::load_matrix_sync(afH[i], p, AG_LDA);
                wmma::load_matrix_sync(afL[i], p + (H_ALO - H_AHI), AG_LDA);
            }
#pragma unroll
            for (int j = 0; j < 4; j++) {
                BF bfH, bfL;
                const __half* p = S + H_BHI + (k16 * 16) * LDB_H + wn * 64 + j * 16;
                wmma::load_matrix_sync(bfH, p, LDB_H);
                wmma::load_matrix_sync(bfL, p + (H_BLO - H_BHI), LDB_H);
#pragma unroll
                for (int i = 0; i < 2; i++) {
                    wmma::mma_sync(c[i][j], afH[i], bfH, c[i][j]);
                    wmma::mma_sync(c[i][j], afH[i], bfL, c[i][j]);
                    wmma::mma_sync(c[i][j], afL[i], bfH, c[i][j]);
                }
            }
        }
        __syncthreads();
    }
}

__device__ __forceinline__ void gm64_load_stage(unsigned sb, const __half* aH,
                                                const __half* aL, const __half* bH,
                                                const __half* bL, int kt, int tid,
                                                int aStride) {
#pragma unroll
    for (int t = 0; t < 2; t++) {
        int idx = tid + t * 256;
        int r = idx >> 2, c8 = idx & 3;
        size_t g = (size_t)r * aStride + kt * 32 + c8 * 8;
        cpa16(sb + (r * AG_LDA + c8 * 8) * 2, aH + g);
        cpa16(sb + (128 * AG_LDA + r * AG_LDA + c8 * 8) * 2, aL + g);
    }
    {
        int r = tid >> 3, c8 = tid & 7;
        size_t g = (size_t)(kt * 32 + r) * ST_HID + c8 * 8;
        cpa16(sb + (B64_BHI + r * LDB64 + c8 * 8) * 2, bH + g);
        cpa16(sb + (B64_BLO + r * LDB64 + c8 * 8) * 2, bL + g);
    }
}

template <int KT>
__device__ __forceinline__ void gemm_mainloop64(
        __half* smh, unsigned sbase, const __half* aH, const __half* aL,
        const __half* bH, const __half* bL, int aStride, int tid,
        int wm, int wn, CF (&c)[2][2]) {
    gm64_load_stage(sbase, aH, aL, bH, bL, 0, tid, aStride);
    CPA_COMMIT();
    for (int kt = 0; kt < KT; kt++) {
        if (kt + 1 < KT) {
            gm64_load_stage(sbase + ((kt + 1) & 1) * STAGE64_H * 2,
                            aH, aL, bH, bL, kt + 1, tid, aStride);
            CPA_COMMIT();
            CPA_WAIT(1);
        } else {
            CPA_WAIT(0);
        }
        __syncthreads();

        const __half* S = smh + (kt & 1) * STAGE64_H;
#pragma unroll
        for (int k16 = 0; k16 < 2; k16++) {
            AF afH[2], afL[2];
#pragma unroll
            for (int i = 0; i < 2; i++) {
                const __half* p = S + (wm * 32 + i * 16) * AG_LDA + k16 * 16;
                wmma::load_matrix_sync(afH[i], p, AG_LDA);
                wmma::load_matrix_sync(afL[i], p + 128 * AG_LDA, AG_LDA);
            }
#pragma unroll
            for (int j = 0; j < 2; j++) {
                BF bfH, bfL;
                const __half* p = S + B64_BHI + (k16 * 16) * LDB64 + wn * 32 + j * 16;
                wmma::load_matrix_sync(bfH, p, LDB64);
                wmma::load_matrix_sync(bfL, p + (B64_BLO - B64_BHI), LDB64);
#pragma unroll
                for (int i = 0; i < 2; i++) {
                    wmma::mma_sync(c[i][j], afH[i], bfH, c[i][j]);
                    wmma::mma_sync(c[i][j], afH[i], bfL, c[i][j]);
                    wmma::mma_sync(c[i][j], afL[i], bfH, c[i][j]);
                }
            }
        }
        __syncthreads();
    }
}

// ---------------------------------------------------------------------------
// agg (layer 2)
// ---------------------------------------------------------------------------
__global__ __launch_bounds__(256, 2)
void agg_wmma(const __half* __restrict__ adjhi, const __half* __restrict__ adjlo,
              const __half* __restrict__ shi, const __half* __restrict__ slo,
              float* __restrict__ oe) {
    extern __shared__ __half smh[];
    const unsigned sbase = (unsigned)__cvta_generic_to_shared(smh);
    const int tid = threadIdx.x;
    const int wid = tid >> 5;
    const int wm = wid >> 1, wn = wid & 1;
    const int m0 = blockIdx.x * 128;
    const int b = blockIdx.y, e = blockIdx.z;

    const __half* aH = adjhi + ((size_t)(b * Eq + e) * Nq + m0) * Nq;
    const __half* aL = adjlo + ((size_t)(b * Eq + e) * Nq + m0) * Nq;
    const __half* bH = shi + (size_t)(b * Eq + e) * Nq * NHID;
    const __half* bL = slo + (size_t)(b * Eq + e) * Nq * NHID;

    CF c[2][4];
#pragma unroll
    for (int i = 0; i < 2; i++)
#pragma unroll
        for (int j = 0; j < 4; j++) wmma::fill_fragment(c[i][j], 0.f);

    gemm_mainloop<Nq / 32>(smh, sbase, aH, aL, bH, bL, Nq, tid, wm, wn, c);

#pragma unroll
    for (int i = 0; i < 2; i++)
#pragma unroll
        for (int j = 0; j < 4; j++) {
#pragma unroll
            for (int t = 0; t < c[i][j].num_elements; t++)
                c[i][j].x[t] = fmaxf(c[i][j].x[t] * SCALE_UP, 0.f);
            float* op = oe + ((size_t)(b * Eq + e) * Nq + m0 + wm * 32 + i * 16) * NHID
                           + wn * 64 + j * 16;
            wmma::store_matrix_sync(op, c[i][j], NHID, wmma::mem_row_major);
        }
}

// ---------------------------------------------------------------------------
// agg64 (layer 3)
// ---------------------------------------------------------------------------
__global__ __launch_bounds__(256, 2)
void agg64_wmma(const __half* __restrict__ adjhi, const __half* __restrict__ adjlo,
                const __half* __restrict__ shi, const __half* __restrict__ slo,
                float* __restrict__ oe64) {
    extern __shared__ __half smh[];
    const unsigned sbase = (unsigned)__cvta_generic_to_shared(smh);
    const int tid = threadIdx.x;
    const int wid = tid >> 5;
    const int wm = wid >> 1, wn = wid & 1;
    const int m0 = blockIdx.x * 128;
    const int b = blockIdx.y, e = blockIdx.z;

    const __half* aH = adjhi + ((size_t)(b * Eq + e) * Nq + m0) * Nq;
    const __half* aL = adjlo + ((size_t)(b * Eq + e) * Nq + m0) * Nq;
    const __half* bH = shi + (size_t)(b * Eq + e) * Nq * ST_HID;
    const __half* bL = slo + (size_t)(b * Eq + e) * Nq * ST_HID;

    CF c[2][2];
#pragma unroll
    for (int i = 0; i < 2; i++)
#pragma unroll
        for (int j = 0; j < 2; j++) wmma::fill_fragment(c[i][j], 0.f);

    gemm_mainloop64<Nq / 32>(smh, sbase, aH, aL, bH, bL, Nq, tid, wm, wn, c);

#pragma unroll
    for (int i = 0; i < 2; i++)
#pragma unroll
        for (int j = 0; j < 2; j++) {
#pragma unroll
            for (int t = 0; t < c[i][j].num_elements; t++)
                c[i][j].x[t] *= SCALE_UP;
            float* op = oe64 + ((size_t)(b * Eq + e) * Nq + m0 + wm * 32 + i * 16) * ST_HID
                             + wn * 32 + j * 16;
            wmma::store_matrix_sync(op, c[i][j], ST_HID, wmma::mem_row_major);
        }
}

// ---------------------------------------------------------------------------
// support23 (layer 2)
// ---------------------------------------------------------------------------
__global__ __launch_bounds__(256, 2)
void support23_wmma(const __half* __restrict__ hhi, const __half* __restrict__ hlo,
                    const __half* __restrict__ whi, const __half* __restrict__ wlo,
                    __half* __restrict__ supphi, __half* __restrict__ supplo) {
    extern __shared__ __half smh[];
    const unsigned sbase = (unsigned)__cvta_generic_to_shared(smh);
    const int tid = threadIdx.x;
    const int wid = tid >> 5, lane = tid & 31;
    const int wm = wid >> 1, wn = wid & 1;
    const int e = blockIdx.y;
    const int m0 = blockIdx.x * 128;
    const int b = m0 / Nq, n0 = m0 % Nq;

    const __half* aH = hhi + (size_t)m0 * NHID;
    const __half* aL = hlo + (size_t)m0 * NHID;
    const __half* bH = whi + (size_t)e * NHID * NHID;
    const __half* bL = wlo + (size_t)e * NHID * NHID;

    CF c[2][4];
#pragma unroll
    for (int i = 0; i < 2; i++)
#pragma unroll
        for (int j = 0; j < 4; j++) wmma::fill_fragment(c[i][j], 0.f);

    gemm_mainloop<NHID / 32>(smh, sbase, aH, aL, bH, bL, NHID, tid, wm, wn, c);

    float* E = (float*)smh + wid * (32 * 68);
#pragma unroll
    for (int i = 0; i < 2; i++)
#pragma unroll
        for (int j = 0; j < 4; j++)
            wmma::store_matrix_sync(E + (i * 16) * 68 + j * 16, c[i][j], 68,
                                    wmma::mem_row_major);
    __syncwarp();
#pragma unroll
    for (int t = 0; t < 16; t++) {
        int p = lane + t * 32;
        int r = p >> 4, c4 = (p & 15) * 4;
        float4 v = *(float4*)&E[r * 68 + c4];
        __half h0, h1, h2, h3, l0, l1, l2, l3;
        split1h(v.x, h0, l0); split1h(v.y, h1, l1);
        split1h(v.z, h2, l2); split1h(v.w, h3, l3);
        size_t o = ((size_t)(b * Eq + e) * Nq + n0 + wm * 32 + r) * NHID + wn * 64 + c4;
        half2 hA = __halves2half2(h0, h1), hB = __halves2half2(h2, h3);
        half2 lA = __halves2half2(l0, l1), lB = __halves2half2(l2, l3);
        uint2 uh, ul;
        uh.x = *(unsigned*)&hA; uh.y = *(unsigned*)&hB;
        ul.x = *(unsigned*)&lA; ul.y = *(unsigned*)&lB;
        *(uint2*)(supphi + o) = uh;
        *(uint2*)(supplo + o) = ul;
    }
}

// ---------------------------------------------------------------------------
// supp3 (layer 3, N=64)
// ---------------------------------------------------------------------------
__global__ __launch_bounds__(256, 2)
void supp3_wmma(const __half* __restrict__ hhi, const __half* __restrict__ hlo,
                const __half* __restrict__ whi, const __half* __restrict__ wlo,
                __half* __restrict__ s64hi, __half* __restrict__ s64lo) {
    extern __shared__ __half smh[];
    const unsigned sbase = (unsigned)__cvta_generic_to_shared(smh);
    const int tid = threadIdx.x;
    const int wid = tid >> 5, lane = tid & 31;
    const int wm = wid >> 1, wn = wid & 1;
    const int e = blockIdx.y;
    const int m0 = blockIdx.x * 128;
    const int b = m0 / Nq, n0 = m0 % Nq;

    const __half* aH = hhi + (size_t)m0 * NHID;
    const __half* aL = hlo + (size_t)m0 * NHID;
    const __half* bH = whi + (size_t)e * NHID * ST_HID;
    const __half* bL = wlo + (size_t)e * NHID * ST_HID;

    CF c[2][2];
#pragma unroll
    for (int i = 0; i < 2; i++)
#pragma unroll
        for (int j = 0; j < 2; j++) wmma::fill_fragment(c[i][j], 0.f);

    gemm_mainloop64<NHID / 32>(smh, sbase, aH, aL, bH, bL, NHID, tid, wm, wn, c);

    float* E = (float*)smh + wid * (32 * 36);
#pragma unroll
    for (int i = 0; i < 2; i++)
#pragma unroll
        for (int j = 0; j < 2; j++)
            wmma::store_matrix_sync(E + (i * 16) * 36 + j * 16, c[i][j], 36,
                                    wmma::mem_row_major);
    __syncwarp();
#pragma unroll
    for (int t = 0; t < 8; t++) {
        int p = lane + t * 32;
        int r = p >> 3, c4 = (p & 7) * 4;
        float4 v = *(float4*)&E[r * 36 + c4];
        __half h0, h1, h2, h3, l0, l1, l2, l3;
        split1h(v.x, h0, l0); split1h(v.y, h1, l1);
        split1h(v.z, h2, l2); split1h(v.w, h3, l3);
        size_t o = ((size_t)(b * Eq + e) * Nq + n0 + wm * 32 + r) * ST_HID + wn * 32 + c4;
        half2 hA = __halves2half2(h0, h1), hB = __halves2half2(h2, h3);
        half2 lA = __halves2half2(l0, l1), lB = __halves2half2(l2, l3);
        uint2 uh, ul;
        uh.x = *(unsigned*)&hA; uh.y = *(unsigned*)&hB;
        ul.x = *(unsigned*)&lA; ul.y = *(unsigned*)&lB;
        *(uint2*)(s64hi + o) = uh;
        *(uint2*)(s64lo + o) = ul;
    }
}

// ---------------------------------------------------------------------------
// agg16_split v3: reg-prefetch + DOUBLE-BUFFERED A stage -> 1 sync per kt.
// Reads fp32 adj; writes adj fp16 hi/lo; t1 = adj @ h0_scaled. grid (3,Bq,Eq)
// ---------------------------------------------------------------------------
__global__ __launch_bounds__(256, 2)
void agg16_split(const float* __restrict__ adjF,
                 __half* __restrict__ adjhi, __half* __restrict__ adjlo,
                 const __half* __restrict__ h0hi, const __half* __restrict__ h0lo,
                 __half* __restrict__ t1hi, __half* __restrict__ t1lo) {
    extern __shared__ __half smh[];
    __half* BHI = smh + A16_BHI;     // resident h0[b]
    __half* BLO = smh + A16_BLO;

    const int tid = threadIdx.x;
    const int wid = tid >> 5, lane = tid & 31;
    const int m0 = blockIdx.x * 128;
    const int b = blockIdx.y, e = blockIdx.z;

    const size_t gbase = ((size_t)(b * Eq + e) * Nq + m0) * Nq;
    const float* aF = adjF + gbase;

    // Resident h0[b]
    {
        const __half* bH = h0hi + (size_t)b * Nq * NFEAT;
        const __half* bL = h0lo + (size_t)b * Nq * NFEAT;
#pragma unroll
        for (int t = 0; t < 3; t++) {
            int i8 = tid + t * 256;
            *(uint4*)&BHI[i8 * 8] = *(const uint4*)(bH + (size_t)i8 * 8);
            *(uint4*)&BLO[i8 * 8] = *(const uint4*)(bL + (size_t)i8 * 8);
        }
    }

    CF acc;
    wmma::fill_fragment(acc, 0.f);

    const int r0 = tid >> 2, c80 = tid & 3;
    const int r1 = (tid + 256) >> 2, c81 = (tid + 256) & 3;

    float4 cur[2][2], nxt[2][2];
    {
        const float* s0 = aF + (size_t)r0 * Nq + c80 * 8;
        const float* s1 = aF + (size_t)r1 * Nq + c81 * 8;
        cur[0][0] = *(const float4*)s0; cur[0][1] = *(const float4*)(s0 + 4);
        cur[1][0] = *(const float4*)s1; cur[1][1] = *(const float4*)(s1 + 4);
    }
    __syncthreads();   // h0 resident

    constexpr int KT = Nq / 32;   // 12
    for (int kt = 0; kt < KT; kt++) {
        if (kt + 1 < KT) {
            const float* s0 = aF + (size_t)r0 * Nq + (kt + 1) * 32 + c80 * 8;
            const float* s1 = aF + (size_t)r1 * Nq + (kt + 1) * 32 + c81 * 8;
            nxt[0][0] = *(const float4*)s0; nxt[0][1] = *(const float4*)(s0 + 4);
            nxt[1][0] = *(const float4*)s1; nxt[1][1] = *(const float4*)(s1 + 4);
        }
        __half* AHI = smh + (kt & 1) * A16_STAGE;
        __half* ALO = AHI + 128 * AG_LDA;
#pragma unroll
        for (int q = 0; q < 2; q++) {
            int rr = q ? r1 : r0, cc = q ? c81 : c80;
            float vv[8] = {cur[q][0].x, cur[q][0].y, cur[q][0].z, cur[q][0].w,
                           cur[q][1].x, cur[q][1].y, cur[q][1].z, cur[q][1].w};
            H8 H, L;
#pragma unroll
            for (int j = 0; j < 8; j++) split1h(vv[j], H.v[j], L.v[j]);
            *(H8*)&AHI[rr * AG_LDA + cc * 8] = H;
            *(H8*)&ALO[rr * AG_LDA + cc * 8] = L;
            size_t go = gbase + (size_t)rr * Nq + kt * 32 + cc * 8;
            *(H8*)(adjhi + go) = H;
            *(H8*)(adjlo + go) = L;
        }
        __syncthreads();    // single sync per kt (stage double-buffered)

#pragma unroll
        for (int k16 = 0; k16 < 2; k16++) {
            AF afH, afL;
            const __half* pa = AHI + (wid * 16) * AG_LDA + k16 * 16;
            wmma::load_matrix_sync(afH, pa, AG_LDA);
            wmma::load_matrix_sync(afL, pa + 128 * AG_LDA, AG_LDA);
            BF bfH, bfL;
            const __half* pb = BHI + (kt * 32 + k16 * 16) * NFEAT;
            wmma::load_matrix_sync(bfH, pb, NFEAT);
            wmma::load_matrix_sync(bfL, pb + (A16_BLO - A16_BHI), NFEAT);
            wmma::mma_sync(acc, afH, bfH, acc);
            wmma::mma_sync(acc, afH, bfL, acc);
            wmma::mma_sync(acc, afL, bfH, acc);
        }
#pragma unroll
        for (int q = 0; q < 2; q++) {
            cur[q][0] = nxt[q][0];
            cur[q][1] = nxt[q][1];
        }
    }

    __syncthreads();
    float* E = (float*)smh + wid * (16 * 20);
    wmma::store_matrix_sync(E, acc, 20, wmma::mem_row_major);
    __syncwarp();
    {
        int r = lane >> 1, c0 = (lane & 1) * 8;
        H8 H, L;
#pragma unroll
        for (int j = 0; j < 8; j++)
            split1h(E[r * 20 + c0 + j], H.v[j], L.v[j]);
        size_t o = ((size_t)(b * Eq + e) * Nq + m0 + wid * 16 + r) * NFEAT + c0;
        *(H8*)(t1hi + o) = H;
        *(H8*)(t1lo + o) = L;
    }
}

// ---------------------------------------------------------------------------
// support1
// ---------------------------------------------------------------------------
__global__ __launch_bounds__(256, 2)
void support1_wmma(const __half* __restrict__ t1hi, const __half* __restrict__ t1lo,
                   const __half* __restrict__ w1hi, const __half* __restrict__ w1lo,
                   float* __restrict__ oe) {
    extern __shared__ __half smh[];
    __half* Ahi = smh + S1_AHI;
    __half* Alo = smh + S1_ALO;
    __half* Bhi = smh + S1_BHI;
    __half* Blo = smh + S1_BLO;

    const int tid = threadIdx.x;
    const int wid = tid >> 5;
    const int wm = wid >> 1, wn = wid & 1;
    const int e = blockIdx.y;
    const int m0 = blockIdx.x * 128;
    const int b = m0 / Nq, n0 = m0 % Nq;

    {
        int r = tid >> 1, c8 = tid & 1;
        size_t g = ((size_t)(b * Eq + e) * Nq + n0 + r) * NFEAT + c8 * 8;
        *(uint4*)&Ahi[r * S1_LDA + c8 * 8] = *(const uint4*)(t1hi + g);
        *(uint4*)&Alo[r * S1_LDA + c8 * 8] = *(const uint4*)(t1lo + g);
    }
    {
        int r = tid >> 4, c8 = tid & 15;
        size_t g = (size_t)(e * NFEAT + r) * NHID + c8 * 8;
        *(uint4*)&Bhi[r * LDB_H + c8 * 8] = *(const uint4*)(w1hi + g);
        *(uint4*)&Blo[r * LDB_H + c8 * 8] = *(const uint4*)(w1lo + g);
    }
    __syncthreads();

    CF c[2][4];
#pragma unroll
    for (int i = 0; i < 2; i++)
#pragma unroll
        for (int j = 0; j < 4; j++) wmma::fill_fragment(c[i][j], 0.f);

    AF afH[2], afL[2];
#pragma unroll
    for (int i = 0; i < 2; i++) {
        const __half* p = Ahi + (wm * 32 + i * 16) * S1_LDA;
        wmma::load_matrix_sync(afH[i], p, S1_LDA);
        wmma::load_matrix_sync(afL[i], p + (S1_ALO - S1_AHI), S1_LDA);
    }
#pragma unroll
    for (int j = 0; j < 4; j++) {
        BF bfH, bfL;
        const __half* p = Bhi + wn * 64 + j * 16;
        wmma::load_matrix_sync(bfH, p, LDB_H);
        wmma::load_matrix_sync(bfL, p + (S1_BLO - S1_BHI), LDB_H);
#pragma unroll
        for (int i = 0; i < 2; i++) {
            wmma::mma_sync(c[i][j], afH[i], bfH, c[i][j]);
            wmma::mma_sync(c[i][j], afH[i], bfL, c[i][j]);
            wmma::mma_sync(c[i][j], afL[i], bfH, c[i][j]);
        }
    }

#pragma unroll
    for (int i = 0; i < 2; i++)
#pragma unroll
        for (int j = 0; j < 4; j++) {
#pragma unroll
            for (int t = 0; t < c[i][j].num_elements; t++)
                c[i][j].x[t] = fmaxf(c[i][j].x[t] * SCALE_UP, 0.f);
            float* op = oe + ((size_t)(b * Eq + e) * Nq + n0 + wm * 32 + i * 16) * NHID
                           + wn * 64 + j * 16;
            wmma::store_matrix_sync(op, c[i][j], NHID, wmma::mem_row_major);
        }
}

// ---------------------------------------------------------------------------
// head64
// ---------------------------------------------------------------------------
__global__ __launch_bounds__(256)
void head64_kernel(const float* __restrict__ oe64,
                   const float* __restrict__ b1,
                   const float* __restrict__ w2, const float* __restrict__ b2,
                   const float* __restrict__ rescale, float* __restrict__ out) {
    __shared__ float z1S[16][ST_HID + 4];

    const int tid = threadIdx.x;
    const int row0 = blockIdx.x * 16;
    const int b = row0 / Nq;
    const int n0 = row0 % Nq;

    const float* base = oe64 + ((size_t)(b * Eq) * Nq + n0) * ST_HID;
    const size_t eS = (size_t)Nq * ST_HID;
    {
        int r = tid >> 4, c4 = (tid & 15) * 4;
        float4 v0 = *(const float4*)(base + (size_t)r * ST_HID + c4);
        float4 v1 = *(const float4*)(base + eS + (size_t)r * ST_HID + c4);
        float4 v2 = *(const float4*)(base + 2 * eS + (size_t)r * ST_HID + c4);
        z1S[r][c4 + 0] = tanhf(v0.x + v1.x + v2.x + b1[c4 + 0]);
        z1S[r][c4 + 1] = tanhf(v0.y + v1.y + v2.y + b1[c4 + 1]);
        z1S[r][c4 + 2] = tanhf(v0.z + v1.z + v2.z + b1[c4 + 2]);
        z1S[r][c4 + 3] = tanhf(v0.w + v1.w + v2.w + b1[c4 + 3]);
    }
    __syncthreads();

    const float ew = expf(rescale[0]);
    for (int p = tid; p < 16 * 32; p += 256) {
        int row = p >> 5, j = p & 31;
        float acc = b2[j];
#pragma unroll 8
        for (int k = 0; k < ST_HID; k++)
            acc += z1S[row][k] * w2[j * ST_HID + k];
        int grow = row0 + row;
        if (j < ST_OUT)
            out[(size_t)grow * ST_OUT + j] = ew * tanhf(acc);
        else
            out[(size_t)MFLAT * ST_OUT + (size_t)grow * ST_OUT + (j - ST_OUT)] = acc;
    }
}

// ---------------------------------------------------------------------------
extern "C" void kernel_launch(void* const* d_in, const int* in_sizes, int n_in,
                              void* d_out, int out_size) {
    const float* x       = (const float*)d_in[0];
    const float* adj     = (const float*)d_in[1];
    const float* emb_w   = (const float*)d_in[2];
    const float* gc1_w   = (const float*)d_in[3];
    const float* gc2_w   = (const float*)d_in[4];
    const float* gc3_w   = (const float*)d_in[5];
    const float* st_w1   = (const float*)d_in[6];
    const float* st_b1   = (const float*)d_in[7];
    const float* st_w2   = (const float*)d_in[8];
    const float* st_b2   = (const float*)d_in[9];
    const float* rescale = (const float*)d_in[10];
    float* out = (float*)d_out;

    __half *adjhi, *adjlo, *supphi, *supplo, *s64hi, *s64lo;
    __half *hhi, *hlo, *h0hi, *h0lo, *t1hi, *t1lo;
    __half *w1hi, *w1lo, *w2hi, *w2lo, *w31hi, *w31lo;
    float* oe;
    cudaGetSymbolAddress((void**)&adjhi,  g_adjhi);
    cudaGetSymbolAddress((void**)&adjlo,  g_adjlo);
    cudaGetSymbolAddress((void**)&supphi, g_supphi);
    cudaGetSymbolAddress((void**)&supplo, g_supplo);
    cudaGetSymbolAddress((void**)&s64hi,  g_s64hi);
    cudaGetSymbolAddress((void**)&s64lo,  g_s64lo);
    cudaGetSymbolAddress((void**)&oe,     g_oe);
    cudaGetSymbolAddress((void**)&hhi,    g_hhi);
    cudaGetSymbolAddress((void**)&hlo,    g_hlo);
    cudaGetSymbolAddress((void**)&h0hi,   g_h0hi);
    cudaGetSymbolAddress((void**)&h0lo,   g_h0lo);
    cudaGetSymbolAddress((void**)&t1hi,   g_t1hi);
    cudaGetSymbolAddress((void**)&t1lo,   g_t1lo);
    cudaGetSymbolAddress((void**)&w1hi,   g_w1hi);
    cudaGetSymbolAddress((void**)&w1lo,   g_w1lo);
    cudaGetSymbolAddress((void**)&w2hi,   g_w2hi);
    cudaGetSymbolAddress((void**)&w2lo,   g_w2lo);
    cudaGetSymbolAddress((void**)&w31hi,  g_w31hi);
    cudaGetSymbolAddress((void**)&w31lo,  g_w31lo);

    cudaFuncSetAttribute(agg_wmma,       cudaFuncAttributeMaxDynamicSharedMemorySize, AG_SMEM);
    cudaFuncSetAttribute(agg64_wmma,     cudaFuncAttributeMaxDynamicSharedMemorySize, A64_SMEM);
    cudaFuncSetAttribute(agg16_split,    cudaFuncAttributeMaxDynamicSharedMemorySize, A16_SMEM);
    cudaFuncSetAttribute(support1_wmma,  cudaFuncAttributeMaxDynamicSharedMemorySize, S1_SMEM);
    cudaFuncSetAttribute(support23_wmma, cudaFuncAttributeMaxDynamicSharedMemorySize, AG_SMEM);
    cudaFuncSetAttribute(supp3_wmma,     cudaFuncAttributeMaxDynamicSharedMemorySize, A64_SMEM);

    dim3 agrid(Nq / 128, Bq, Eq);     // (3, 64, 3)
    dim3 sgrid(MFLAT / 128, Eq);      // (192, 3)
    const int hsumBlocks = (MFLAT * NHID) / (256 * 8);

    // prep: 3 launches so ncu (-s 5, 2 harness front-runs) captures agg16_split
    prep_w_kernel<<<W2BLK + W1BLK, 256>>>(gc2_w, gc1_w, w2hi, w2lo, w1hi, w1lo);
    prep_w31_kernel<<<(Eq * NHID * ST_HID) / 256, 256>>>(gc3_w, st_w1, w31hi, w31lo);
    prep_h0_kernel<<<(MFLAT * NFEAT) / 256, 256>>>(emb_w, x, h0hi, h0lo);

    // Layer 1
    agg16_split<<<agrid, 256, A16_SMEM>>>(adj, adjhi, adjlo, h0hi, h0lo, t1hi, t1lo);
    support1_wmma<<<sgrid, 256, S1_SMEM>>>(t1hi, t1lo, w1hi, w1lo, oe);
    // Layer 2
    hsum_split_kernel<<<hsumBlocks, 256>>>(oe, hhi, hlo);
    support23_wmma<<<sgrid, 256, AG_SMEM>>>(hhi, hlo, w2hi, w2lo, supphi, supplo);
    agg_wmma<<<agrid, 256, AG_SMEM>>>(adjhi, adjlo, supphi, supplo, oe);
    // Layer 3
    hsum_split_kernel<<<hsumBlocks, 256>>>(oe, hhi, hlo);
    supp3_wmma<<<sgrid, 256, A64_SMEM>>>(hhi, hlo, w31hi, w31lo, s64hi, s64lo);
    agg64_wmma<<<agrid, 256, A64_SMEM>>>(adjhi, adjlo, s64hi, s64lo, oe);
    // Head
    head64_kernel<<<MFLAT / 16, 256>>>(oe, st_b1, st_w2, st_b2, rescale, out);
}